// round 6
// baseline (speedup 1.0000x reference)
#include <cuda_runtime.h>
#include <math.h>

#define BATCH 32
#define CIN 512
#define HID 64
#define PLANE 4096            // floats per (b,c) plane
#define PLANE4 1024           // float4s per plane
#define NKNOT 12
#define NBASE 8
#define NPLANES (BATCH * CIN)     // 16384
#define NEIGHTH (NPLANES * 8)     // 131072 eighth-plane tasks

#define NTHREADS 512
#define MINBLK 3
#define NBLOCKS (148 * MINBLK)               // 444, all resident by launch_bounds
#define NWARPS (NBLOCKS * (NTHREADS / 32))   // 7104
#define TOT_F4 (NPLANES * PLANE4)            // 16777216

// Scratch (no device allocations allowed)
__device__ float g_part8[NEIGHTH];        // eighth-plane partial sums
__device__ float g_h2silu[BATCH * HID];   // silu(silu(y1))
__device__ float g_b2[BATCH * HID * NBASE];
__device__ float g_gate[BATCH * CIN];

__device__ unsigned int g_bar_count = 0;
__device__ volatile unsigned int g_bar_gen = 0;

__device__ __forceinline__ void grid_barrier() {
    __threadfence();
    __syncthreads();
    if (threadIdx.x == 0) {
        unsigned int gen = g_bar_gen;
        unsigned int old = atomicAdd(&g_bar_count, 1u);
        if (old == NBLOCKS - 1) {
            g_bar_count = 0;
            __threadfence();
            g_bar_gen = gen + 1;
        } else {
            while (g_bar_gen == gen) { __nanosleep(32); }
        }
        __threadfence();
    }
    __syncthreads();
}

__device__ __forceinline__ float siluf(float v) {
    return v / (1.0f + __expf(-v));
}

// Cox-de Boor, mirroring the reference recursion. 12 knots -> 8 order-3 bases.
__device__ __forceinline__ void bspline8(float x, const float* t, float* out) {
    float b[11];
#pragma unroll
    for (int j = 0; j < 11; j++)
        b[j] = (x >= t[j] && x < t[j + 1]) ? 1.0f : 0.0f;
#pragma unroll
    for (int k = 1; k <= 3; k++) {
#pragma unroll
        for (int j = 0; j < 10; j++) {
            if (j <= 10 - k) {
                float left  = (x - t[j]) / (t[j + k] - t[j]) * b[j];
                float right = (t[j + k + 1] - x) / (t[j + k + 1] - t[j + 1]) * b[j + 1];
                b[j] = left + right;
            }
        }
    }
#pragma unroll
    for (int j = 0; j < NBASE; j++) out[j] = b[j];
}

__global__ void __launch_bounds__(NTHREADS, MINBLK) kanse_persistent(
    const float4* __restrict__ x,
    const float* __restrict__ grid1, const float* __restrict__ bw1,
    const float* __restrict__ sw1,  const float* __restrict__ sc1,
    const float* __restrict__ grid2, const float* __restrict__ bw2,
    const float* __restrict__ sw2,  const float* __restrict__ sc2,
    float4* __restrict__ out) {

    const int lane = threadIdx.x & 31;
    const int w = blockIdx.x * (NTHREADS / 32) + (threadIdx.x >> 5);

    // ===== Phase 1: eighth-plane partial sums (131072 warp tasks) =====
    for (int e = w; e < NEIGHTH; e += NWARPS) {
        const int plane = e >> 3;
        const int sub   = e & 7;
        const float4* p = x + (size_t)plane * PLANE4 + sub * 128;
        float4 r0 = __ldcs(&p[lane]);
        float4 r1 = __ldcs(&p[32 + lane]);
        float4 r2 = __ldcs(&p[64 + lane]);
        float4 r3 = __ldcs(&p[96 + lane]);
        float sum = ((r0.x + r0.y) + (r0.z + r0.w)) + ((r1.x + r1.y) + (r1.z + r1.w))
                  + ((r2.x + r2.y) + (r2.z + r2.w)) + ((r3.x + r3.y) + (r3.z + r3.w));
#pragma unroll
        for (int off = 16; off >= 1; off >>= 1)
            sum += __shfl_xor_sync(0xffffffffu, sum, off);
        if (lane == 0) g_part8[e] = sum;
    }

    grid_barrier();

    // ===== Phase 2a: layer 1 (warp per (b,o)); combine partials + prep inline
    if (w < BATCH * HID) {
        const int b = w >> 6;
        const int o = w & (HID - 1);
        float t1[NKNOT];
#pragma unroll
        for (int j = 0; j < NKNOT; j++) t1[j] = grid1[j];  // rows identical (make_grid)

        const float4* sw4 = (const float4*)(sw1 + (size_t)o * CIN * NBASE);
        const float*  bwr = bw1 + o * CIN;
        const float*  scr = sc1 + o * CIN;

        float acc = 0.0f;
        for (int it = 0; it < 16; it++) {
            const int c = lane + 32 * it;
            const float4* pp = (const float4*)(g_part8 + (size_t)(b * CIN + c) * 8);
            float4 pa = pp[0];
            float4 pb = pp[1];
            float m = (((pa.x + pa.y) + (pa.z + pa.w))
                     + ((pb.x + pb.y) + (pb.z + pb.w))) * (1.0f / (float)PLANE);
            if (isnan(m)) m = 0.0f;
            m = fminf(fmaxf(m, -3.402823466e38f), 3.402823466e38f);

            float bb[NBASE];
            bspline8(m, t1, bb);

            float4 wa = sw4[c * 2];
            float4 wb = sw4[c * 2 + 1];
            float sp = bb[0] * wa.x + bb[1] * wa.y + bb[2] * wa.z + bb[3] * wa.w
                     + bb[4] * wb.x + bb[5] * wb.y + bb[6] * wb.z + bb[7] * wb.w;
            acc += siluf(m) * bwr[c] + sp * scr[c];
        }
#pragma unroll
        for (int off = 16; off >= 1; off >>= 1)
            acc += __shfl_xor_sync(0xffffffffu, acc, off);

        if (lane == 0) {
            float h = siluf(acc);                 // inter-layer activation
            g_h2silu[b * HID + o] = siluf(h);     // layer-2 base path
            float t2[NKNOT];
#pragma unroll
            for (int j = 0; j < NKNOT; j++) t2[j] = grid2[j];
            float bb2[NBASE];
            bspline8(h, t2, bb2);
#pragma unroll
            for (int k = 0; k < NBASE; k++)
                g_b2[(b * HID + o) * NBASE + k] = bb2[k];
        }
    }

    grid_barrier();

    // ===== Phase 2b: layer 2 + sigmoid (warp per (b,c)) =====
    for (int t = w; t < BATCH * CIN; t += NWARPS) {
        const int b = t >> 9;
        const int c = t & (CIN - 1);
        const int j0 = lane * 2;
        const float4* sw4 = (const float4*)(sw2 + (size_t)c * HID * NBASE);
        const float4* b24 = (const float4*)(g_b2 + (size_t)b * HID * NBASE);

        float4 w0 = sw4[j0 * 2];
        float4 w1 = sw4[j0 * 2 + 1];
        float4 w2 = sw4[j0 * 2 + 2];
        float4 w3 = sw4[j0 * 2 + 3];
        float4 c0 = b24[j0 * 2];
        float4 c1 = b24[j0 * 2 + 1];
        float4 c2 = b24[j0 * 2 + 2];
        float4 c3 = b24[j0 * 2 + 3];
        float sp0 = c0.x * w0.x + c0.y * w0.y + c0.z * w0.z + c0.w * w0.w
                  + c1.x * w1.x + c1.y * w1.y + c1.z * w1.z + c1.w * w1.w;
        float sp1 = c2.x * w2.x + c2.y * w2.y + c2.z * w2.z + c2.w * w2.w
                  + c3.x * w3.x + c3.y * w3.y + c3.z * w3.z + c3.w * w3.w;
        float2 bw = *(const float2*)(bw2 + c * HID + j0);
        float2 sc = *(const float2*)(sc2 + c * HID + j0);
        float2 h2 = *(const float2*)(g_h2silu + b * HID + j0);
        float acc = h2.x * bw.x + sp0 * sc.x + h2.y * bw.y + sp1 * sc.y;
#pragma unroll
        for (int off = 16; off >= 1; off >>= 1)
            acc += __shfl_xor_sync(0xffffffffu, acc, off);
        if (lane == 0)
            g_gate[t] = 1.0f / (1.0f + __expf(-acc));
    }

    grid_barrier();

    // ===== Phase 3: out = x * gate (flat grid-stride, 4-way unroll) =====
    {
        const int tid = blockIdx.x * NTHREADS + threadIdx.x;
        const int stride = NBLOCKS * NTHREADS;          // 227328
        int idx = tid;
        for (; idx + 3 * stride < TOT_F4; idx += 4 * stride) {
            int i0 = idx, i1 = idx + stride, i2 = idx + 2 * stride, i3 = idx + 3 * stride;
            float4 v0 = __ldcs(&x[i0]);
            float4 v1 = __ldcs(&x[i1]);
            float4 v2 = __ldcs(&x[i2]);
            float4 v3 = __ldcs(&x[i3]);
            float g0 = g_gate[i0 >> 10];
            float g1 = g_gate[i1 >> 10];
            float g2 = g_gate[i2 >> 10];
            float g3 = g_gate[i3 >> 10];
            v0.x *= g0; v0.y *= g0; v0.z *= g0; v0.w *= g0;
            v1.x *= g1; v1.y *= g1; v1.z *= g1; v1.w *= g1;
            v2.x *= g2; v2.y *= g2; v2.z *= g2; v2.w *= g2;
            v3.x *= g3; v3.y *= g3; v3.z *= g3; v3.w *= g3;
            __stcs(&out[i0], v0);
            __stcs(&out[i1], v1);
            __stcs(&out[i2], v2);
            __stcs(&out[i3], v3);
        }
        for (; idx < TOT_F4; idx += stride) {
            float4 v = __ldcs(&x[idx]);
            float g = g_gate[idx >> 10];
            v.x *= g; v.y *= g; v.z *= g; v.w *= g;
            __stcs(&out[idx], v);
        }
    }
}

extern "C" void kernel_launch(void* const* d_in, const int* in_sizes, int n_in,
                              void* d_out, int out_size) {
    const float* x     = (const float*)d_in[0];
    const float* grid1 = (const float*)d_in[1];
    const float* bw1   = (const float*)d_in[2];
    const float* sw1   = (const float*)d_in[3];
    const float* sc1   = (const float*)d_in[4];
    const float* grid2 = (const float*)d_in[5];
    const float* bw2   = (const float*)d_in[6];
    const float* sw2   = (const float*)d_in[7];
    const float* sc2   = (const float*)d_in[8];
    float* out = (float*)d_out;

    kanse_persistent<<<NBLOCKS, NTHREADS>>>(
        (const float4*)x, grid1, bw1, sw1, sc1,
        grid2, bw2, sw2, sc2, (float4*)out);
}

// round 7
// speedup vs baseline: 1.3926x; 1.3926x over previous
#include <cuda_runtime.h>
#include <math.h>

#define BATCH 32
#define CIN 512
#define HID 64
#define PLANE 4096
#define PLANE4 1024
#define NBASE 8
#define NPLANES (BATCH * CIN)     // 16384
#define NEIGHTH (NPLANES * 8)     // 131072 eighth-plane warp tasks

#define NTHREADS 256
#define MINBLK 8
#define NBLOCKS (148 * MINBLK)               // 1184, all resident
#define NWARPS (NBLOCKS * (NTHREADS / 32))   // 9472
#define TOT_F4 (NPLANES * PLANE4)            // 16777216

// Uniform grid constants: h = 12/5 = 2.4, t0 = -6 - 3h = -13.2
#define KNOT_T0   (-13.2f)
#define KNOT_INVH (1.0f / 2.4f)

// Scratch (no device allocations allowed)
__device__ float  g_part8[NEIGHTH];
__device__ float  g_h2silu[BATCH * HID];
__device__ float4 g_b2f4[BATCH * HID];   // 4 nonzero layer-2 bases
__device__ int    g_b2i[BATCH * HID];    // first nonzero basis index
__device__ float  g_gate[BATCH * CIN];

__device__ unsigned int g_bar_count = 0;
__device__ volatile unsigned int g_bar_gen = 0;

__device__ __forceinline__ void grid_barrier() {
    __threadfence();
    __syncthreads();
    if (threadIdx.x == 0) {
        unsigned int gen = g_bar_gen;
        unsigned int old = atomicAdd(&g_bar_count, 1u);
        if (old == NBLOCKS - 1) {
            g_bar_count = 0;
            __threadfence();
            g_bar_gen = gen + 1;
        } else {
            while (g_bar_gen == gen) { __nanosleep(32); }
        }
        __threadfence();
    }
    __syncthreads();
}

__device__ __forceinline__ float siluf(float v) {
    return v / (1.0f + __expf(-v));
}

// Uniform-knot cubic B-spline: returns the 4 nonzero bases and the index of
// the first one. Exactly equivalent to the reference Cox-de Boor recursion
// on make_grid's uniform knots (all other bases are exactly zero).
__device__ __forceinline__ float4 bspline4(float x, int* jbase) {
    float u = (x - KNOT_T0) * KNOT_INVH;
    float fi = floorf(u);
    float f = u - fi;
    float omf = 1.0f - f;
    float f2 = f * f;
    float f3 = f2 * f;
    float4 r;
    r.x = omf * omf * omf * (1.0f / 6.0f);
    r.y = (3.0f * f3 - 6.0f * f2 + 4.0f) * (1.0f / 6.0f);
    r.z = (-3.0f * f3 + 3.0f * f2 + 3.0f * f + 1.0f) * (1.0f / 6.0f);
    r.w = f3 * (1.0f / 6.0f);
    *jbase = (int)fi - 3;
    return r;
}

// Guarded spline dot: sum of 4 bases times weights w[jb..jb+3], skipping
// indices outside [0, NBASE).
__device__ __forceinline__ float spline_dot(float4 bs, int jb, const float* w) {
    float s = 0.0f;
    if (jb >= 0 && jb < NBASE)         s += bs.x * w[jb];
    if (jb + 1 >= 0 && jb + 1 < NBASE) s += bs.y * w[jb + 1];
    if (jb + 2 >= 0 && jb + 2 < NBASE) s += bs.z * w[jb + 2];
    if (jb + 3 >= 0 && jb + 3 < NBASE) s += bs.w * w[jb + 3];
    return s;
}

__global__ void __launch_bounds__(NTHREADS, MINBLK) kanse_persistent(
    const float4* __restrict__ x,
    const float* __restrict__ grid1, const float* __restrict__ bw1,
    const float* __restrict__ sw1,  const float* __restrict__ sc1,
    const float* __restrict__ grid2, const float* __restrict__ bw2,
    const float* __restrict__ sw2,  const float* __restrict__ sc2,
    float4* __restrict__ out) {

    const int lane = threadIdx.x & 31;
    const int w = blockIdx.x * (NTHREADS / 32) + (threadIdx.x >> 5);

    // ===== Phase 1: eighth-plane partial sums =====
    for (int e = w; e < NEIGHTH; e += NWARPS) {
        const float4* p = x + (size_t)e * 128;
        float4 r0 = p[lane];
        float4 r1 = p[32 + lane];
        float4 r2 = p[64 + lane];
        float4 r3 = p[96 + lane];
        float sum = ((r0.x + r0.y) + (r0.z + r0.w)) + ((r1.x + r1.y) + (r1.z + r1.w))
                  + ((r2.x + r2.y) + (r2.z + r2.w)) + ((r3.x + r3.y) + (r3.z + r3.w));
#pragma unroll
        for (int off = 16; off >= 1; off >>= 1)
            sum += __shfl_xor_sync(0xffffffffu, sum, off);
        if (lane == 0) g_part8[e] = sum;
    }

    grid_barrier();

    // ===== Phase 2a: layer 1 (warp per (b,o)) with inline mean/prep =====
    if (w < BATCH * HID) {
        const int b = w >> 6;
        const int o = w & (HID - 1);
        const float* swrow = sw1 + (size_t)o * CIN * NBASE;
        const float* bwr   = bw1 + o * CIN;
        const float* scr   = sc1 + o * CIN;

        float acc = 0.0f;
        for (int it = 0; it < 16; it++) {
            const int c = lane + 32 * it;
            const float4* pp = (const float4*)(g_part8 + (size_t)(b * CIN + c) * 8);
            float4 pa = pp[0];
            float4 pb = pp[1];
            float m = (((pa.x + pa.y) + (pa.z + pa.w))
                     + ((pb.x + pb.y) + (pb.z + pb.w))) * (1.0f / (float)PLANE);
            if (isnan(m)) m = 0.0f;

            int jb;
            float4 bs = bspline4(m, &jb);
            float sp = spline_dot(bs, jb, swrow + c * NBASE);
            acc += siluf(m) * bwr[c] + sp * scr[c];
        }
#pragma unroll
        for (int off = 16; off >= 1; off >>= 1)
            acc += __shfl_xor_sync(0xffffffffu, acc, off);

        if (lane == 0) {
            float h = siluf(acc);
            g_h2silu[b * HID + o] = siluf(h);
            int jb;
            float4 bs = bspline4(h, &jb);
            g_b2f4[b * HID + o] = bs;
            g_b2i[b * HID + o] = jb;
        }
    }

    grid_barrier();

    // ===== Phase 2b: layer 2 + sigmoid (warp per (b,c)) =====
    for (int t = w; t < BATCH * CIN; t += NWARPS) {
        const int b = t >> 9;
        const int c = t & (CIN - 1);
        const int j0 = lane * 2;
        const float* swrow = sw2 + (size_t)c * HID * NBASE;

        float4 bs0 = g_b2f4[b * HID + j0];
        float4 bs1 = g_b2f4[b * HID + j0 + 1];
        int jb0 = g_b2i[b * HID + j0];
        int jb1 = g_b2i[b * HID + j0 + 1];
        float sp0 = spline_dot(bs0, jb0, swrow + j0 * NBASE);
        float sp1 = spline_dot(bs1, jb1, swrow + (j0 + 1) * NBASE);

        float2 bw = *(const float2*)(bw2 + c * HID + j0);
        float2 sc = *(const float2*)(sc2 + c * HID + j0);
        float2 h2 = *(const float2*)(g_h2silu + b * HID + j0);
        float acc = h2.x * bw.x + sp0 * sc.x + h2.y * bw.y + sp1 * sc.y;
#pragma unroll
        for (int off = 16; off >= 1; off >>= 1)
            acc += __shfl_xor_sync(0xffffffffu, acc, off);
        if (lane == 0)
            g_gate[t] = 1.0f / (1.0f + __expf(-acc));
    }

    grid_barrier();

    // ===== Phase 3: out = x * gate (flat grid-stride, 4 loads in flight) =====
    {
        const int tid = blockIdx.x * NTHREADS + threadIdx.x;
        const int stride = NBLOCKS * NTHREADS;          // 303104
        int idx = tid;
        for (; idx + 3 * stride < TOT_F4; idx += 4 * stride) {
            int i0 = idx, i1 = idx + stride, i2 = idx + 2 * stride, i3 = idx + 3 * stride;
            float4 v0 = x[i0];
            float4 v1 = x[i1];
            float4 v2 = x[i2];
            float4 v3 = x[i3];
            float g0 = g_gate[i0 >> 10];
            float g1 = g_gate[i1 >> 10];
            float g2 = g_gate[i2 >> 10];
            float g3 = g_gate[i3 >> 10];
            v0.x *= g0; v0.y *= g0; v0.z *= g0; v0.w *= g0;
            v1.x *= g1; v1.y *= g1; v1.z *= g1; v1.w *= g1;
            v2.x *= g2; v2.y *= g2; v2.z *= g2; v2.w *= g2;
            v3.x *= g3; v3.y *= g3; v3.z *= g3; v3.w *= g3;
            out[i0] = v0;
            out[i1] = v1;
            out[i2] = v2;
            out[i3] = v3;
        }
        for (; idx < TOT_F4; idx += stride) {
            float4 v = x[idx];
            float g = g_gate[idx >> 10];
            v.x *= g; v.y *= g; v.z *= g; v.w *= g;
            out[idx] = v;
        }
    }
}

extern "C" void kernel_launch(void* const* d_in, const int* in_sizes, int n_in,
                              void* d_out, int out_size) {
    const float* x     = (const float*)d_in[0];
    const float* grid1 = (const float*)d_in[1];
    const float* bw1   = (const float*)d_in[2];
    const float* sw1   = (const float*)d_in[3];
    const float* sc1   = (const float*)d_in[4];
    const float* grid2 = (const float*)d_in[5];
    const float* bw2   = (const float*)d_in[6];
    const float* sw2   = (const float*)d_in[7];
    const float* sc2   = (const float*)d_in[8];
    float* out = (float*)d_out;

    kanse_persistent<<<NBLOCKS, NTHREADS>>>(
        (const float4*)x, grid1, bw1, sw1, sc1,
        grid2, bw2, sw2, sc2, (float4*)out);
}

// round 8
// speedup vs baseline: 1.4029x; 1.0074x over previous
#include <cuda_runtime.h>
#include <math.h>

#define BATCH 32
#define CIN 512
#define HID 64
#define PLANE 4096
#define PLANE4 1024
#define NBASE 8
#define NPLANES (BATCH * CIN)     // 16384
#define NEIGHTH (NPLANES * 8)     // 131072 eighth-plane warp tasks

#define NTHREADS 256
#define MINBLK 8
#define NBLOCKS (148 * MINBLK)               // 1184, all resident
#define NWARPS (NBLOCKS * (NTHREADS / 32))   // 9472
#define TOT_F4 (NPLANES * PLANE4)            // 16777216

// Uniform grid: h = 12/5 = 2.4, t0 = -6 - 3h = -13.2
#define KNOT_T0   (-13.2f)
#define KNOT_INVH (1.0f / 2.4f)

// Scratch (no device allocations allowed)
__device__ float  g_part8[NEIGHTH];
__device__ float  g_h2silu[BATCH * HID];
__device__ float4 g_b2[BATCH * HID * 2];   // 8 layer-2 bases per (b,o)
__device__ float  g_gate[BATCH * CIN];

__device__ unsigned int g_bar_count = 0;
__device__ volatile unsigned int g_bar_gen = 0;

__device__ __forceinline__ void grid_barrier() {
    __threadfence();
    __syncthreads();
    if (threadIdx.x == 0) {
        unsigned int gen = g_bar_gen;
        unsigned int old = atomicAdd(&g_bar_count, 1u);
        if (old == NBLOCKS - 1) {
            g_bar_count = 0;
            __threadfence();
            g_bar_gen = gen + 1;
        } else {
            while (g_bar_gen == gen) { __nanosleep(32); }
        }
        __threadfence();
    }
    __syncthreads();
}

__device__ __forceinline__ float siluf(float v) {
    return v / (1.0f + __expf(-v));
}

// One uniform cubic B-spline basis value: q(clamp(u-j,0,4)).
// Exactly equals the reference Cox-de Boor recursion on make_grid's knots.
__device__ __forceinline__ float ubasis(float u, float j) {
    float v = fminf(fmaxf(u - j, 0.0f), 4.0f);
    float m1 = fmaxf(v - 1.0f, 0.0f);
    float m2 = fmaxf(v - 2.0f, 0.0f);
    float m3 = fmaxf(v - 3.0f, 0.0f);
    return (v * v * v - 4.0f * m1 * m1 * m1 + 6.0f * m2 * m2 * m2
            - 4.0f * m3 * m3 * m3) * (1.0f / 6.0f);
}

// Dot of all 8 bases at x with weight row (2 float4s). No data-dependent
// addressing: the weight loads are hoistable above the computation.
__device__ __forceinline__ float spline_dot8(float x, float4 wa, float4 wb) {
    float u = (x - KNOT_T0) * KNOT_INVH;
    return ubasis(u, 0.0f) * wa.x + ubasis(u, 1.0f) * wa.y
         + ubasis(u, 2.0f) * wa.z + ubasis(u, 3.0f) * wa.w
         + ubasis(u, 4.0f) * wb.x + ubasis(u, 5.0f) * wb.y
         + ubasis(u, 6.0f) * wb.z + ubasis(u, 7.0f) * wb.w;
}

__global__ void __launch_bounds__(NTHREADS, MINBLK) kanse_persistent(
    const float4* __restrict__ x,
    const float* __restrict__ grid1, const float* __restrict__ bw1,
    const float* __restrict__ sw1,  const float* __restrict__ sc1,
    const float* __restrict__ grid2, const float* __restrict__ bw2,
    const float* __restrict__ sw2,  const float* __restrict__ sc2,
    float4* __restrict__ out) {

    const int lane = threadIdx.x & 31;
    const int w = blockIdx.x * (NTHREADS / 32) + (threadIdx.x >> 5);

    // ===== Phase 1: eighth-plane partial sums =====
    for (int e = w; e < NEIGHTH; e += NWARPS) {
        const float4* p = x + (size_t)e * 128;
        float4 r0 = p[lane];
        float4 r1 = p[32 + lane];
        float4 r2 = p[64 + lane];
        float4 r3 = p[96 + lane];
        float sum = ((r0.x + r0.y) + (r0.z + r0.w)) + ((r1.x + r1.y) + (r1.z + r1.w))
                  + ((r2.x + r2.y) + (r2.z + r2.w)) + ((r3.x + r3.y) + (r3.z + r3.w));
#pragma unroll
        for (int off = 16; off >= 1; off >>= 1)
            sum += __shfl_xor_sync(0xffffffffu, sum, off);
        if (lane == 0) g_part8[e] = sum;
    }

    grid_barrier();

    // ===== Phase 2a: layer 1 (warp per (b,o)); mean-combine + prep inline ===
    if (w < BATCH * HID) {
        const int b = w >> 6;
        const int o = w & (HID - 1);
        const float4* sw4 = (const float4*)(sw1 + (size_t)o * CIN * NBASE);
        const float*  bwr = bw1 + o * CIN;
        const float*  scr = sc1 + o * CIN;

        float acc = 0.0f;
#pragma unroll 4
        for (int it = 0; it < 16; it++) {
            const int c = lane + 32 * it;
            // All addresses below are data-independent -> hoistable loads.
            const float4* pp = (const float4*)(g_part8 + (size_t)(b * CIN + c) * 8);
            float4 pa = pp[0];
            float4 pb = pp[1];
            float4 wa = sw4[c * 2];
            float4 wb = sw4[c * 2 + 1];
            float bwv = bwr[c];
            float scv = scr[c];

            float m = (((pa.x + pa.y) + (pa.z + pa.w))
                     + ((pb.x + pb.y) + (pb.z + pb.w))) * (1.0f / (float)PLANE);
            if (isnan(m)) m = 0.0f;

            acc += siluf(m) * bwv + spline_dot8(m, wa, wb) * scv;
        }
#pragma unroll
        for (int off = 16; off >= 1; off >>= 1)
            acc += __shfl_xor_sync(0xffffffffu, acc, off);

        if (lane == 0) {
            float h = siluf(acc);
            g_h2silu[b * HID + o] = siluf(h);
            float u = (h - KNOT_T0) * KNOT_INVH;
            float4 ba, bb;
            ba.x = ubasis(u, 0.0f); ba.y = ubasis(u, 1.0f);
            ba.z = ubasis(u, 2.0f); ba.w = ubasis(u, 3.0f);
            bb.x = ubasis(u, 4.0f); bb.y = ubasis(u, 5.0f);
            bb.z = ubasis(u, 6.0f); bb.w = ubasis(u, 7.0f);
            g_b2[(b * HID + o) * 2]     = ba;
            g_b2[(b * HID + o) * 2 + 1] = bb;
        }
    }

    grid_barrier();

    // ===== Phase 2b: layer 2 + sigmoid (warp per (b,c)) =====
    for (int t = w; t < BATCH * CIN; t += NWARPS) {
        const int b = t >> 9;
        const int c = t & (CIN - 1);
        const int j0 = lane * 2;
        const float4* sw4 = (const float4*)(sw2 + (size_t)c * HID * NBASE);

        float4 w0 = sw4[j0 * 2];
        float4 w1 = sw4[j0 * 2 + 1];
        float4 w2 = sw4[j0 * 2 + 2];
        float4 w3 = sw4[j0 * 2 + 3];
        float4 c0 = g_b2[(b * HID + j0) * 2];
        float4 c1 = g_b2[(b * HID + j0) * 2 + 1];
        float4 c2 = g_b2[(b * HID + j0 + 1) * 2];
        float4 c3 = g_b2[(b * HID + j0 + 1) * 2 + 1];
        float sp0 = c0.x * w0.x + c0.y * w0.y + c0.z * w0.z + c0.w * w0.w
                  + c1.x * w1.x + c1.y * w1.y + c1.z * w1.z + c1.w * w1.w;
        float sp1 = c2.x * w2.x + c2.y * w2.y + c2.z * w2.z + c2.w * w2.w
                  + c3.x * w3.x + c3.y * w3.y + c3.z * w3.z + c3.w * w3.w;
        float2 bw = *(const float2*)(bw2 + c * HID + j0);
        float2 sc = *(const float2*)(sc2 + c * HID + j0);
        float2 h2 = *(const float2*)(g_h2silu + b * HID + j0);
        float acc = h2.x * bw.x + sp0 * sc.x + h2.y * bw.y + sp1 * sc.y;
#pragma unroll
        for (int off = 16; off >= 1; off >>= 1)
            acc += __shfl_xor_sync(0xffffffffu, acc, off);
        if (lane == 0)
            g_gate[t] = 1.0f / (1.0f + __expf(-acc));
    }

    grid_barrier();

    // ===== Phase 3: out = x * gate (flat grid-stride, 4 loads in flight) =====
    {
        const int tid = blockIdx.x * NTHREADS + threadIdx.x;
        const int stride = NBLOCKS * NTHREADS;          // 303104
        int idx = tid;
        for (; idx + 3 * stride < TOT_F4; idx += 4 * stride) {
            int i0 = idx, i1 = idx + stride, i2 = idx + 2 * stride, i3 = idx + 3 * stride;
            float4 v0 = x[i0];
            float4 v1 = x[i1];
            float4 v2 = x[i2];
            float4 v3 = x[i3];
            float g0 = g_gate[i0 >> 10];
            float g1 = g_gate[i1 >> 10];
            float g2 = g_gate[i2 >> 10];
            float g3 = g_gate[i3 >> 10];
            v0.x *= g0; v0.y *= g0; v0.z *= g0; v0.w *= g0;
            v1.x *= g1; v1.y *= g1; v1.z *= g1; v1.w *= g1;
            v2.x *= g2; v2.y *= g2; v2.z *= g2; v2.w *= g2;
            v3.x *= g3; v3.y *= g3; v3.z *= g3; v3.w *= g3;
            out[i0] = v0;
            out[i1] = v1;
            out[i2] = v2;
            out[i3] = v3;
        }
        for (; idx < TOT_F4; idx += stride) {
            float4 v = x[idx];
            float g = g_gate[idx >> 10];
            v.x *= g; v.y *= g; v.z *= g; v.w *= g;
            out[idx] = v;
        }
    }
}

extern "C" void kernel_launch(void* const* d_in, const int* in_sizes, int n_in,
                              void* d_out, int out_size) {
    const float* x     = (const float*)d_in[0];
    const float* grid1 = (const float*)d_in[1];
    const float* bw1   = (const float*)d_in[2];
    const float* sw1   = (const float*)d_in[3];
    const float* sc1   = (const float*)d_in[4];
    const float* grid2 = (const float*)d_in[5];
    const float* bw2   = (const float*)d_in[6];
    const float* sw2   = (const float*)d_in[7];
    const float* sc2   = (const float*)d_in[8];
    float* out = (float*)d_out;

    kanse_persistent<<<NBLOCKS, NTHREADS>>>(
        (const float4*)x, grid1, bw1, sw1, sc1,
        grid2, bw2, sw2, sc2, (float4*)out);
}

// round 9
// speedup vs baseline: 1.4239x; 1.0150x over previous
#include <cuda_runtime.h>
#include <math.h>

#define BATCH 32
#define CIN 512
#define HID 64
#define PLANE 4096
#define PLANE4 1024
#define NBASE 8
#define NPLANES (BATCH * CIN)     // 16384
#define NEIGHTH (NPLANES * 8)     // 131072 eighth-plane tasks

#define NTHREADS 256
#define MINBLK 8
#define NBLOCKS (148 * MINBLK)               // 1184, all resident
#define NWARPS (NBLOCKS * (NTHREADS / 32))   // 9472
#define TOT_F4 (NPLANES * PLANE4)            // 16777216

#define CH1 32     // eighth-planes per block grab (4 per warp)
#define CH3 1024   // float4s per block grab (4 per thread)

// Uniform grid: h = 12/5 = 2.4, t0 = -6 - 3h = -13.2
#define KNOT_T0   (-13.2f)
#define KNOT_INVH (1.0f / 2.4f)

// Scratch (no device allocations allowed)
__device__ float  g_part8[NEIGHTH];
__device__ float  g_h2silu[BATCH * HID];
__device__ float4 g_b2[BATCH * HID * 2];
__device__ float  g_gate[BATCH * CIN];

__device__ unsigned int g_ctr1 = 0;   // phase-1 work counter
__device__ unsigned int g_ctr3 = 0;   // phase-3 work counter
__device__ unsigned int g_done = 0;   // end-of-kernel reset rendezvous
__device__ unsigned int g_bar_count = 0;
__device__ volatile unsigned int g_bar_gen = 0;

__device__ __forceinline__ void grid_barrier() {
    __threadfence();
    __syncthreads();
    if (threadIdx.x == 0) {
        unsigned int gen = g_bar_gen;
        unsigned int old = atomicAdd(&g_bar_count, 1u);
        if (old == NBLOCKS - 1) {
            g_bar_count = 0;
            __threadfence();
            g_bar_gen = gen + 1;
        } else {
            while (g_bar_gen == gen) { __nanosleep(32); }
        }
        __threadfence();
    }
    __syncthreads();
}

__device__ __forceinline__ float siluf(float v) {
    return v / (1.0f + __expf(-v));
}

// One uniform cubic B-spline basis: q(clamp(u-j,0,4)); exactly matches the
// reference Cox-de Boor recursion on make_grid's uniform knots.
__device__ __forceinline__ float ubasis(float u, float j) {
    float v = fminf(fmaxf(u - j, 0.0f), 4.0f);
    float m1 = fmaxf(v - 1.0f, 0.0f);
    float m2 = fmaxf(v - 2.0f, 0.0f);
    float m3 = fmaxf(v - 3.0f, 0.0f);
    return (v * v * v - 4.0f * m1 * m1 * m1 + 6.0f * m2 * m2 * m2
            - 4.0f * m3 * m3 * m3) * (1.0f / 6.0f);
}

__device__ __forceinline__ float spline_dot8(float x, float4 wa, float4 wb) {
    float u = (x - KNOT_T0) * KNOT_INVH;
    return ubasis(u, 0.0f) * wa.x + ubasis(u, 1.0f) * wa.y
         + ubasis(u, 2.0f) * wa.z + ubasis(u, 3.0f) * wa.w
         + ubasis(u, 4.0f) * wb.x + ubasis(u, 5.0f) * wb.y
         + ubasis(u, 6.0f) * wb.z + ubasis(u, 7.0f) * wb.w;
}

__global__ void __launch_bounds__(NTHREADS, MINBLK) kanse_persistent(
    const float4* __restrict__ x,
    const float* __restrict__ grid1, const float* __restrict__ bw1,
    const float* __restrict__ sw1,  const float* __restrict__ sc1,
    const float* __restrict__ grid2, const float* __restrict__ bw2,
    const float* __restrict__ sw2,  const float* __restrict__ sc2,
    float4* __restrict__ out) {

    const int lane = threadIdx.x & 31;
    const int wid  = threadIdx.x >> 5;
    const int w = blockIdx.x * (NTHREADS / 32) + wid;

    __shared__ unsigned int sh_base;

    // ===== Phase 1: eighth-plane partial sums (dynamic chunks) =====
    for (;;) {
        __syncthreads();
        if (threadIdx.x == 0) sh_base = atomicAdd(&g_ctr1, (unsigned)CH1);
        __syncthreads();
        unsigned base = sh_base;
        if (base >= NEIGHTH) break;
#pragma unroll
        for (int k = 0; k < 4; k++) {
            const int e = base + wid * 4 + k;
            const float4* p = x + (size_t)e * 128;
            float4 r0 = p[lane];
            float4 r1 = p[32 + lane];
            float4 r2 = p[64 + lane];
            float4 r3 = p[96 + lane];
            float sum = ((r0.x + r0.y) + (r0.z + r0.w)) + ((r1.x + r1.y) + (r1.z + r1.w))
                      + ((r2.x + r2.y) + (r2.z + r2.w)) + ((r3.x + r3.y) + (r3.z + r3.w));
#pragma unroll
            for (int off = 16; off >= 1; off >>= 1)
                sum += __shfl_xor_sync(0xffffffffu, sum, off);
            if (lane == 0) g_part8[e] = sum;
        }
    }

    grid_barrier();

    // ===== Phase 2a: layer 1 (warp per (b,o)); mean-combine + prep inline ===
    if (w < BATCH * HID) {
        const int b = w >> 6;
        const int o = w & (HID - 1);
        const float4* sw4 = (const float4*)(sw1 + (size_t)o * CIN * NBASE);
        const float*  bwr = bw1 + o * CIN;
        const float*  scr = sc1 + o * CIN;

        float acc = 0.0f;
#pragma unroll 4
        for (int it = 0; it < 16; it++) {
            const int c = lane + 32 * it;
            const float4* pp = (const float4*)(g_part8 + (size_t)(b * CIN + c) * 8);
            float4 pa = pp[0];
            float4 pb = pp[1];
            float4 wa = sw4[c * 2];
            float4 wb = sw4[c * 2 + 1];
            float bwv = bwr[c];
            float scv = scr[c];

            float m = (((pa.x + pa.y) + (pa.z + pa.w))
                     + ((pb.x + pb.y) + (pb.z + pb.w))) * (1.0f / (float)PLANE);
            if (isnan(m)) m = 0.0f;

            acc += siluf(m) * bwv + spline_dot8(m, wa, wb) * scv;
        }
#pragma unroll
        for (int off = 16; off >= 1; off >>= 1)
            acc += __shfl_xor_sync(0xffffffffu, acc, off);

        if (lane == 0) {
            float h = siluf(acc);
            g_h2silu[b * HID + o] = siluf(h);
            float u = (h - KNOT_T0) * KNOT_INVH;
            float4 ba, bb;
            ba.x = ubasis(u, 0.0f); ba.y = ubasis(u, 1.0f);
            ba.z = ubasis(u, 2.0f); ba.w = ubasis(u, 3.0f);
            bb.x = ubasis(u, 4.0f); bb.y = ubasis(u, 5.0f);
            bb.z = ubasis(u, 6.0f); bb.w = ubasis(u, 7.0f);
            g_b2[(b * HID + o) * 2]     = ba;
            g_b2[(b * HID + o) * 2 + 1] = bb;
        }
    }

    grid_barrier();

    // ===== Phase 2b: layer 2 + sigmoid (warp per (b,c), static) =====
    for (int t = w; t < BATCH * CIN; t += NWARPS) {
        const int b = t >> 9;
        const int c = t & (CIN - 1);
        const int j0 = lane * 2;
        const float4* sw4 = (const float4*)(sw2 + (size_t)c * HID * NBASE);

        float4 w0 = sw4[j0 * 2];
        float4 w1 = sw4[j0 * 2 + 1];
        float4 w2 = sw4[j0 * 2 + 2];
        float4 w3 = sw4[j0 * 2 + 3];
        float4 c0 = g_b2[(b * HID + j0) * 2];
        float4 c1 = g_b2[(b * HID + j0) * 2 + 1];
        float4 c2 = g_b2[(b * HID + j0 + 1) * 2];
        float4 c3 = g_b2[(b * HID + j0 + 1) * 2 + 1];
        float sp0 = c0.x * w0.x + c0.y * w0.y + c0.z * w0.z + c0.w * w0.w
                  + c1.x * w1.x + c1.y * w1.y + c1.z * w1.z + c1.w * w1.w;
        float sp1 = c2.x * w2.x + c2.y * w2.y + c2.z * w2.z + c2.w * w2.w
                  + c3.x * w3.x + c3.y * w3.y + c3.z * w3.z + c3.w * w3.w;
        float2 bw = *(const float2*)(bw2 + c * HID + j0);
        float2 sc = *(const float2*)(sc2 + c * HID + j0);
        float2 h2 = *(const float2*)(g_h2silu + b * HID + j0);
        float acc = h2.x * bw.x + sp0 * sc.x + h2.y * bw.y + sp1 * sc.y;
#pragma unroll
        for (int off = 16; off >= 1; off >>= 1)
            acc += __shfl_xor_sync(0xffffffffu, acc, off);
        if (lane == 0)
            g_gate[t] = 1.0f / (1.0f + __expf(-acc));
    }

    grid_barrier();

    // ===== Phase 3: out = x * gate (dynamic chunks, 4 loads in flight) =====
    for (;;) {
        __syncthreads();
        if (threadIdx.x == 0) sh_base = atomicAdd(&g_ctr3, (unsigned)CH3);
        __syncthreads();
        unsigned base = sh_base;
        if (base >= (unsigned)TOT_F4) break;
        int i0 = base + threadIdx.x;
        int i1 = i0 + 256;
        int i2 = i0 + 512;
        int i3 = i0 + 768;
        float4 v0 = x[i0];
        float4 v1 = x[i1];
        float4 v2 = x[i2];
        float4 v3 = x[i3];
        float g0 = g_gate[i0 >> 10];
        float g1 = g_gate[i1 >> 10];
        float g2 = g_gate[i2 >> 10];
        float g3 = g_gate[i3 >> 10];
        v0.x *= g0; v0.y *= g0; v0.z *= g0; v0.w *= g0;
        v1.x *= g1; v1.y *= g1; v1.z *= g1; v1.w *= g1;
        v2.x *= g2; v2.y *= g2; v2.z *= g2; v2.w *= g2;
        v3.x *= g3; v3.y *= g3; v3.z *= g3; v3.w *= g3;
        out[i0] = v0;
        out[i1] = v1;
        out[i2] = v2;
        out[i3] = v3;
    }

    // ===== Reset counters for the next graph replay (last block does it) ====
    __syncthreads();
    if (threadIdx.x == 0) {
        __threadfence();
        unsigned int old = atomicAdd(&g_done, 1u);
        if (old == NBLOCKS - 1) {
            g_ctr1 = 0;
            g_ctr3 = 0;
            g_done = 0;
            __threadfence();
        }
    }
}

extern "C" void kernel_launch(void* const* d_in, const int* in_sizes, int n_in,
                              void* d_out, int out_size) {
    const float* x     = (const float*)d_in[0];
    const float* grid1 = (const float*)d_in[1];
    const float* bw1   = (const float*)d_in[2];
    const float* sw1   = (const float*)d_in[3];
    const float* sc1   = (const float*)d_in[4];
    const float* grid2 = (const float*)d_in[5];
    const float* bw2   = (const float*)d_in[6];
    const float* sw2   = (const float*)d_in[7];
    const float* sc2   = (const float*)d_in[8];
    float* out = (float*)d_out;

    kanse_persistent<<<NBLOCKS, NTHREADS>>>(
        (const float4*)x, grid1, bw1, sw1, sc1,
        grid2, bw2, sw2, sc2, (float4*)out);
}

// round 10
// speedup vs baseline: 1.5257x; 1.0715x over previous
#include <cuda_runtime.h>
#include <math.h>

#define BATCH 32
#define CIN 512
#define HID 64
#define PLANE 4096
#define PLANE4 1024
#define NBASE 8
#define NPLANES (BATCH * CIN)     // 16384
#define NEIGHTH (NPLANES * 8)     // 131072 eighth-plane tasks

#define NTHREADS 256
#define MINBLK 8
#define NBLOCKS (148 * MINBLK)               // 1184, all resident
#define NWARPS (NBLOCKS * (NTHREADS / 32))   // 9472

#define CH1 32     // eighth-planes per block grab in phase 1 (4 per warp)
#define CH3 8      // planes per block grab in phase 3 (1 per warp)

// Uniform grid: h = 12/5 = 2.4, t0 = -6 - 3h = -13.2
#define KNOT_T0   (-13.2f)
#define KNOT_INVH (1.0f / 2.4f)

// Scratch (no device allocations allowed)
__device__ float  g_part8[NEIGHTH];
__device__ float  g_h2silu[BATCH * HID];
__device__ float4 g_b2[BATCH * HID * 2];

__device__ unsigned int g_ctr1 = 0;
__device__ unsigned int g_ctr3 = 0;
__device__ unsigned int g_done = 0;
__device__ unsigned int g_bar_count = 0;
__device__ volatile unsigned int g_bar_gen = 0;

__device__ __forceinline__ void grid_barrier() {
    __threadfence();
    __syncthreads();
    if (threadIdx.x == 0) {
        unsigned int gen = g_bar_gen;
        unsigned int old = atomicAdd(&g_bar_count, 1u);
        if (old == NBLOCKS - 1) {
            g_bar_count = 0;
            __threadfence();
            g_bar_gen = gen + 1;
        } else {
            while (g_bar_gen == gen) { __nanosleep(32); }
        }
        __threadfence();
    }
    __syncthreads();
}

__device__ __forceinline__ float siluf(float v) {
    return v / (1.0f + __expf(-v));
}

// One uniform cubic B-spline basis: q(clamp(u-j,0,4)); exactly matches the
// reference Cox-de Boor recursion on make_grid's uniform knots.
__device__ __forceinline__ float ubasis(float u, float j) {
    float v = fminf(fmaxf(u - j, 0.0f), 4.0f);
    float m1 = fmaxf(v - 1.0f, 0.0f);
    float m2 = fmaxf(v - 2.0f, 0.0f);
    float m3 = fmaxf(v - 3.0f, 0.0f);
    return (v * v * v - 4.0f * m1 * m1 * m1 + 6.0f * m2 * m2 * m2
            - 4.0f * m3 * m3 * m3) * (1.0f / 6.0f);
}

__device__ __forceinline__ float spline_dot8(float x, float4 wa, float4 wb) {
    float u = (x - KNOT_T0) * KNOT_INVH;
    return ubasis(u, 0.0f) * wa.x + ubasis(u, 1.0f) * wa.y
         + ubasis(u, 2.0f) * wa.z + ubasis(u, 3.0f) * wa.w
         + ubasis(u, 4.0f) * wb.x + ubasis(u, 5.0f) * wb.y
         + ubasis(u, 6.0f) * wb.z + ubasis(u, 7.0f) * wb.w;
}

__global__ void __launch_bounds__(NTHREADS, MINBLK) kanse_persistent(
    const float4* __restrict__ x,
    const float* __restrict__ grid1, const float* __restrict__ bw1,
    const float* __restrict__ sw1,  const float* __restrict__ sc1,
    const float* __restrict__ grid2, const float* __restrict__ bw2,
    const float* __restrict__ sw2,  const float* __restrict__ sc2,
    float4* __restrict__ out) {

    const int lane = threadIdx.x & 31;
    const int wid  = threadIdx.x >> 5;
    const int w = blockIdx.x * (NTHREADS / 32) + wid;

    __shared__ unsigned int sh_base;

    // ===== Phase 1: eighth-plane partial sums, REVERSE order ===============
    // (last-read bytes = head of x = L2-resident when phase 3 starts)
    for (;;) {
        __syncthreads();
        if (threadIdx.x == 0) sh_base = atomicAdd(&g_ctr1, (unsigned)CH1);
        __syncthreads();
        unsigned base = sh_base;
        if (base >= NEIGHTH) break;
        unsigned rbase = NEIGHTH - CH1 - base;   // reverse mapping
#pragma unroll
        for (int k = 0; k < 4; k++) {
            const int e = rbase + wid * 4 + k;
            const float4* p = x + (size_t)e * 128;
            float4 r0 = p[lane];
            float4 r1 = p[32 + lane];
            float4 r2 = p[64 + lane];
            float4 r3 = p[96 + lane];
            float sum = ((r0.x + r0.y) + (r0.z + r0.w)) + ((r1.x + r1.y) + (r1.z + r1.w))
                      + ((r2.x + r2.y) + (r2.z + r2.w)) + ((r3.x + r3.y) + (r3.z + r3.w));
#pragma unroll
            for (int off = 16; off >= 1; off >>= 1)
                sum += __shfl_xor_sync(0xffffffffu, sum, off);
            if (lane == 0) g_part8[e] = sum;
        }
    }

    grid_barrier();

    // ===== Phase 2a: layer 1 (warp per (b,o)); mean-combine + prep inline ===
    if (w < BATCH * HID) {
        const int b = w >> 6;
        const int o = w & (HID - 1);
        const float4* sw4 = (const float4*)(sw1 + (size_t)o * CIN * NBASE);
        const float*  bwr = bw1 + o * CIN;
        const float*  scr = sc1 + o * CIN;

        float acc = 0.0f;
#pragma unroll 4
        for (int it = 0; it < 16; it++) {
            const int c = lane + 32 * it;
            const float4* pp = (const float4*)(g_part8 + (size_t)(b * CIN + c) * 8);
            float4 pa = pp[0];
            float4 pb = pp[1];
            float4 wa = sw4[c * 2];
            float4 wb = sw4[c * 2 + 1];
            float bwv = bwr[c];
            float scv = scr[c];

            float m = (((pa.x + pa.y) + (pa.z + pa.w))
                     + ((pb.x + pb.y) + (pb.z + pb.w))) * (1.0f / (float)PLANE);
            if (isnan(m)) m = 0.0f;

            acc += siluf(m) * bwv + spline_dot8(m, wa, wb) * scv;
        }
#pragma unroll
        for (int off = 16; off >= 1; off >>= 1)
            acc += __shfl_xor_sync(0xffffffffu, acc, off);

        if (lane == 0) {
            float h = siluf(acc);
            g_h2silu[b * HID + o] = siluf(h);
            float u = (h - KNOT_T0) * KNOT_INVH;
            float4 ba, bb;
            ba.x = ubasis(u, 0.0f); ba.y = ubasis(u, 1.0f);
            ba.z = ubasis(u, 2.0f); ba.w = ubasis(u, 3.0f);
            bb.x = ubasis(u, 4.0f); bb.y = ubasis(u, 5.0f);
            bb.z = ubasis(u, 6.0f); bb.w = ubasis(u, 7.0f);
            g_b2[(b * HID + o) * 2]     = ba;
            g_b2[(b * HID + o) * 2 + 1] = bb;
        }
    }

    grid_barrier();

    // ===== Phase 3: inline layer2+sigmoid per plane, then apply =============
    // Warp owns plane (b,c); gate(b,c) is used by exactly this plane.
    for (;;) {
        __syncthreads();
        if (threadIdx.x == 0) sh_base = atomicAdd(&g_ctr3, (unsigned)CH3);
        __syncthreads();
        unsigned base = sh_base;
        if (base >= (unsigned)NPLANES) break;
        const int plane = base + wid;
        const int b = plane >> 9;
        const int c = plane & (CIN - 1);

        // ---- gate(b,c): 64-dot with spline path (lane covers j0, j0+1) ----
        const int j0 = lane * 2;
        const float4* sw4 = (const float4*)(sw2 + (size_t)c * HID * NBASE);
        float4 w0 = sw4[j0 * 2];
        float4 w1 = sw4[j0 * 2 + 1];
        float4 w2 = sw4[j0 * 2 + 2];
        float4 w3 = sw4[j0 * 2 + 3];
        float4 c0 = g_b2[(b * HID + j0) * 2];
        float4 c1 = g_b2[(b * HID + j0) * 2 + 1];
        float4 c2 = g_b2[(b * HID + j0 + 1) * 2];
        float4 c3 = g_b2[(b * HID + j0 + 1) * 2 + 1];
        float sp0 = c0.x * w0.x + c0.y * w0.y + c0.z * w0.z + c0.w * w0.w
                  + c1.x * w1.x + c1.y * w1.y + c1.z * w1.z + c1.w * w1.w;
        float sp1 = c2.x * w2.x + c2.y * w2.y + c2.z * w2.z + c2.w * w2.w
                  + c3.x * w3.x + c3.y * w3.y + c3.z * w3.z + c3.w * w3.w;
        float2 bw = *(const float2*)(bw2 + c * HID + j0);
        float2 sc = *(const float2*)(sc2 + c * HID + j0);
        float2 h2 = *(const float2*)(g_h2silu + b * HID + j0);
        float acc = h2.x * bw.x + sp0 * sc.x + h2.y * bw.y + sp1 * sc.y;
#pragma unroll
        for (int off = 16; off >= 1; off >>= 1)
            acc += __shfl_xor_sync(0xffffffffu, acc, off);
        const float g = 1.0f / (1.0f + __expf(-acc));

        // ---- stream the plane: 8 iterations of 4 float4 per lane ----------
        const float4* p = x + (size_t)plane * PLANE4;
        float4* q = out + (size_t)plane * PLANE4;
#pragma unroll
        for (int it = 0; it < 8; it++) {
            const int o0 = it * 128 + lane;
            float4 v0 = p[o0];
            float4 v1 = p[o0 + 32];
            float4 v2 = p[o0 + 64];
            float4 v3 = p[o0 + 96];
            v0.x *= g; v0.y *= g; v0.z *= g; v0.w *= g;
            v1.x *= g; v1.y *= g; v1.z *= g; v1.w *= g;
            v2.x *= g; v2.y *= g; v2.z *= g; v2.w *= g;
            v3.x *= g; v3.y *= g; v3.z *= g; v3.w *= g;
            __stcs(&q[o0], v0);
            __stcs(&q[o0 + 32], v1);
            __stcs(&q[o0 + 64], v2);
            __stcs(&q[o0 + 96], v3);
        }
    }

    // ===== Reset counters for next graph replay (last block) ================
    __syncthreads();
    if (threadIdx.x == 0) {
        __threadfence();
        unsigned int old = atomicAdd(&g_done, 1u);
        if (old == NBLOCKS - 1) {
            g_ctr1 = 0;
            g_ctr3 = 0;
            g_done = 0;
            __threadfence();
        }
    }
}

extern "C" void kernel_launch(void* const* d_in, const int* in_sizes, int n_in,
                              void* d_out, int out_size) {
    const float* x     = (const float*)d_in[0];
    const float* grid1 = (const float*)d_in[1];
    const float* bw1   = (const float*)d_in[2];
    const float* sw1   = (const float*)d_in[3];
    const float* sc1   = (const float*)d_in[4];
    const float* grid2 = (const float*)d_in[5];
    const float* bw2   = (const float*)d_in[6];
    const float* sw2   = (const float*)d_in[7];
    const float* sc2   = (const float*)d_in[8];
    float* out = (float*)d_out;

    kanse_persistent<<<NBLOCKS, NTHREADS>>>(
        (const float4*)x, grid1, bw1, sw1, sc1,
        grid2, bw2, sw2, sc2, (float4*)out);
}

// round 11
// speedup vs baseline: 1.5450x; 1.0126x over previous
#include <cuda_runtime.h>
#include <math.h>

#define BATCH 32
#define CIN 512
#define HID 64
#define PLANE 4096
#define PLANE4 1024
#define NBASE 8
#define NPLANES (BATCH * CIN)     // 16384
#define NHALF (NPLANES * 2)       // 32768 half-plane tasks

#define NTHREADS 256
#define MINBLK 5
#define NBLOCKS (148 * MINBLK)               // 740, all resident
#define NWARPS (NBLOCKS * (NTHREADS / 32))   // 5920

#define CH1 32    // half-plane tasks per block grab (4 per warp)
#define CH3 8     // planes per block grab (1 per warp)

// Uniform grid: h = 12/5 = 2.4, t0 = -6 - 3h = -13.2
#define KNOT_T0   (-13.2f)
#define KNOT_INVH (1.0f / 2.4f)

// Scratch (no device allocations allowed)
__device__ float  g_part2[NHALF];
__device__ float  g_h2silu[BATCH * HID];
__device__ float4 g_b2[BATCH * HID * 2];

__device__ unsigned int g_ctr1 = 0;
__device__ unsigned int g_ctr3 = 0;
__device__ unsigned int g_done = 0;
__device__ unsigned int g_bar_count = 0;
__device__ volatile unsigned int g_bar_gen = 0;

__device__ __forceinline__ void grid_barrier() {
    __threadfence();
    __syncthreads();
    if (threadIdx.x == 0) {
        unsigned int gen = g_bar_gen;
        unsigned int old = atomicAdd(&g_bar_count, 1u);
        if (old == NBLOCKS - 1) {
            g_bar_count = 0;
            __threadfence();
            g_bar_gen = gen + 1;
        } else {
            while (g_bar_gen == gen) { __nanosleep(32); }
        }
        __threadfence();
    }
    __syncthreads();
}

__device__ __forceinline__ float siluf(float v) {
    return v / (1.0f + __expf(-v));
}

// One uniform cubic B-spline basis: q(clamp(u-j,0,4)); exactly matches the
// reference Cox-de Boor recursion on make_grid's uniform knots.
__device__ __forceinline__ float ubasis(float u, float j) {
    float v = fminf(fmaxf(u - j, 0.0f), 4.0f);
    float m1 = fmaxf(v - 1.0f, 0.0f);
    float m2 = fmaxf(v - 2.0f, 0.0f);
    float m3 = fmaxf(v - 3.0f, 0.0f);
    return (v * v * v - 4.0f * m1 * m1 * m1 + 6.0f * m2 * m2 * m2
            - 4.0f * m3 * m3 * m3) * (1.0f / 6.0f);
}

__device__ __forceinline__ float spline_dot8(float x, float4 wa, float4 wb) {
    float u = (x - KNOT_T0) * KNOT_INVH;
    return ubasis(u, 0.0f) * wa.x + ubasis(u, 1.0f) * wa.y
         + ubasis(u, 2.0f) * wa.z + ubasis(u, 3.0f) * wa.w
         + ubasis(u, 4.0f) * wb.x + ubasis(u, 5.0f) * wb.y
         + ubasis(u, 6.0f) * wb.z + ubasis(u, 7.0f) * wb.w;
}

__global__ void __launch_bounds__(NTHREADS, MINBLK) kanse_persistent(
    const float4* __restrict__ x,
    const float* __restrict__ grid1, const float* __restrict__ bw1,
    const float* __restrict__ sw1,  const float* __restrict__ sc1,
    const float* __restrict__ grid2, const float* __restrict__ bw2,
    const float* __restrict__ sw2,  const float* __restrict__ sc2,
    float4* __restrict__ out) {

    const int lane = threadIdx.x & 31;
    const int wid  = threadIdx.x >> 5;
    const int w = blockIdx.x * (NTHREADS / 32) + wid;

    __shared__ unsigned int sh_base;

    // ===== Phase 1: half-plane partial sums, REVERSE order, depth-8 loads ===
    for (;;) {
        __syncthreads();
        if (threadIdx.x == 0) sh_base = atomicAdd(&g_ctr1, (unsigned)CH1);
        __syncthreads();
        unsigned base = sh_base;
        if (base >= NHALF) break;
        unsigned rbase = NHALF - CH1 - base;   // reverse mapping for L2 tail reuse
#pragma unroll
        for (int k = 0; k < 4; k++) {
            const int e = rbase + wid * 4 + k;
            const float4* p = x + (size_t)e * 512;
            float sum = 0.0f;
#pragma unroll
            for (int half = 0; half < 2; half++) {
                float4 r[8];
#pragma unroll
                for (int u = 0; u < 8; u++)
                    r[u] = p[half * 256 + u * 32 + lane];
#pragma unroll
                for (int u = 0; u < 8; u++)
                    sum += (r[u].x + r[u].y) + (r[u].z + r[u].w);
            }
#pragma unroll
            for (int off = 16; off >= 1; off >>= 1)
                sum += __shfl_xor_sync(0xffffffffu, sum, off);
            if (lane == 0) g_part2[e] = sum;
        }
    }

    grid_barrier();

    // ===== Phase 2a: layer 1 (warp per (b,o)); mean-combine + prep inline ===
    if (w < BATCH * HID) {
        const int b = w >> 6;
        const int o = w & (HID - 1);
        const float4* sw4 = (const float4*)(sw1 + (size_t)o * CIN * NBASE);
        const float*  bwr = bw1 + o * CIN;
        const float*  scr = sc1 + o * CIN;

        float acc = 0.0f;
#pragma unroll 4
        for (int it = 0; it < 16; it++) {
            const int c = lane + 32 * it;
            float2 pr = *(const float2*)(g_part2 + (size_t)(b * CIN + c) * 2);
            float4 wa = sw4[c * 2];
            float4 wb = sw4[c * 2 + 1];
            float bwv = bwr[c];
            float scv = scr[c];

            float m = (pr.x + pr.y) * (1.0f / (float)PLANE);
            if (isnan(m)) m = 0.0f;

            acc += siluf(m) * bwv + spline_dot8(m, wa, wb) * scv;
        }
#pragma unroll
        for (int off = 16; off >= 1; off >>= 1)
            acc += __shfl_xor_sync(0xffffffffu, acc, off);

        if (lane == 0) {
            float h = siluf(acc);
            g_h2silu[b * HID + o] = siluf(h);
            float u = (h - KNOT_T0) * KNOT_INVH;
            float4 ba, bb;
            ba.x = ubasis(u, 0.0f); ba.y = ubasis(u, 1.0f);
            ba.z = ubasis(u, 2.0f); ba.w = ubasis(u, 3.0f);
            bb.x = ubasis(u, 4.0f); bb.y = ubasis(u, 5.0f);
            bb.z = ubasis(u, 6.0f); bb.w = ubasis(u, 7.0f);
            g_b2[(b * HID + o) * 2]     = ba;
            g_b2[(b * HID + o) * 2 + 1] = bb;
        }
    }

    grid_barrier();

    // ===== Phase 3: inline layer2+sigmoid per plane, then depth-8 stream ====
    for (;;) {
        __syncthreads();
        if (threadIdx.x == 0) sh_base = atomicAdd(&g_ctr3, (unsigned)CH3);
        __syncthreads();
        unsigned base = sh_base;
        if (base >= (unsigned)NPLANES) break;
        const int plane = base + wid;
        const int b = plane >> 9;
        const int c = plane & (CIN - 1);

        // ---- gate(b,c): 64-dot with spline path (lane covers j0, j0+1) ----
        const int j0 = lane * 2;
        const float4* sw4 = (const float4*)(sw2 + (size_t)c * HID * NBASE);
        float4 w0 = sw4[j0 * 2];
        float4 w1 = sw4[j0 * 2 + 1];
        float4 w2 = sw4[j0 * 2 + 2];
        float4 w3 = sw4[j0 * 2 + 3];
        float4 c0 = g_b2[(b * HID + j0) * 2];
        float4 c1 = g_b2[(b * HID + j0) * 2 + 1];
        float4 c2 = g_b2[(b * HID + j0 + 1) * 2];
        float4 c3 = g_b2[(b * HID + j0 + 1) * 2 + 1];
        float sp0 = c0.x * w0.x + c0.y * w0.y + c0.z * w0.z + c0.w * w0.w
                  + c1.x * w1.x + c1.y * w1.y + c1.z * w1.z + c1.w * w1.w;
        float sp1 = c2.x * w2.x + c2.y * w2.y + c2.z * w2.z + c2.w * w2.w
                  + c3.x * w3.x + c3.y * w3.y + c3.z * w3.z + c3.w * w3.w;
        float2 bw = *(const float2*)(bw2 + c * HID + j0);
        float2 sc = *(const float2*)(sc2 + c * HID + j0);
        float2 h2 = *(const float2*)(g_h2silu + b * HID + j0);
        float acc = h2.x * bw.x + sp0 * sc.x + h2.y * bw.y + sp1 * sc.y;
#pragma unroll
        for (int off = 16; off >= 1; off >>= 1)
            acc += __shfl_xor_sync(0xffffffffu, acc, off);
        const float g = 1.0f / (1.0f + __expf(-acc));

        // ---- stream the plane: 4 iterations of 8 front-batched float4 ------
        const float4* p = x + (size_t)plane * PLANE4;
        float4* q = out + (size_t)plane * PLANE4;
#pragma unroll
        for (int it = 0; it < 4; it++) {
            const int o0 = it * 256 + lane;
            float4 r[8];
#pragma unroll
            for (int u = 0; u < 8; u++)
                r[u] = p[o0 + u * 32];
#pragma unroll
            for (int u = 0; u < 8; u++) {
                r[u].x *= g; r[u].y *= g; r[u].z *= g; r[u].w *= g;
                __stcs(&q[o0 + u * 32], r[u]);
            }
        }
    }

    // ===== Reset counters for next graph replay (last block) ================
    __syncthreads();
    if (threadIdx.x == 0) {
        __threadfence();
        unsigned int old = atomicAdd(&g_done, 1u);
        if (old == NBLOCKS - 1) {
            g_ctr1 = 0;
            g_ctr3 = 0;
            g_done = 0;
            __threadfence();
        }
    }
}

extern "C" void kernel_launch(void* const* d_in, const int* in_sizes, int n_in,
                              void* d_out, int out_size) {
    const float* x     = (const float*)d_in[0];
    const float* grid1 = (const float*)d_in[1];
    const float* bw1   = (const float*)d_in[2];
    const float* sw1   = (const float*)d_in[3];
    const float* sc1   = (const float*)d_in[4];
    const float* grid2 = (const float*)d_in[5];
    const float* bw2   = (const float*)d_in[6];
    const float* sw2   = (const float*)d_in[7];
    const float* sc2   = (const float*)d_in[8];
    float* out = (float*)d_out;

    kanse_persistent<<<NBLOCKS, NTHREADS>>>(
        (const float4*)x, grid1, bw1, sw1, sc1,
        grid2, bw2, sw2, sc2, (float4*)out);
}